// round 5
// baseline (speedup 1.0000x reference)
#include <cuda_runtime.h>

#define N_NODES 50000
#define N_EDGES 1600000
#define D 128

// Scratch (allocation-free rule: __device__ globals)
__device__ float g_buf0[N_NODES * D];
__device__ float g_buf1[N_NODES * D];
__device__ int   g_cnt[N_NODES];          // in-degree histogram
__device__ int   g_rank[N_EDGES];         // edge rank within its dst list
__device__ int   g_rowptr[N_NODES + 1];
__device__ int   g_csr_src[N_EDGES];
__device__ float g_norm[N_NODES];

// ---------------------------------------------------------------------------
// Degree histogram + per-edge rank (atomic return value).
// ---------------------------------------------------------------------------
__global__ void k_deg_rank(const int* __restrict__ dst) {
    int e = blockIdx.x * blockDim.x + threadIdx.x;
    if (e < N_EDGES) {
        g_rank[e] = atomicAdd(&g_cnt[dst[e]], 1);
    }
}

// ---------------------------------------------------------------------------
// Fused exclusive scan of g_cnt -> g_rowptr, plus norm = clip(deg,1)^-0.5.
// Single block, 1024 threads, each owns 49 contiguous elements.
// ---------------------------------------------------------------------------
#define SCAN_T 1024
#define SCAN_PER 49   // 1024*49 = 50176 >= 50000
__global__ void __launch_bounds__(SCAN_T) k_scan() {
    __shared__ int warp_sums[32];
    int t = threadIdx.x;
    int base = t * SCAN_PER;

    // pass A: local sum
    int s = 0;
#pragma unroll 7
    for (int j = 0; j < SCAN_PER; j++) {
        int i = base + j;
        if (i < N_NODES) s += g_cnt[i];
    }

    // block-wide exclusive scan of s
    int lane = t & 31;
    int wid  = t >> 5;
    int v = s;
#pragma unroll
    for (int off = 1; off < 32; off <<= 1) {
        int u = __shfl_up_sync(0xffffffffu, v, off);
        if (lane >= off) v += u;
    }
    // v = inclusive warp scan
    if (lane == 31) warp_sums[wid] = v;
    __syncthreads();
    if (wid == 0) {
        int w = (lane < 32) ? warp_sums[lane] : 0;
        int wv = w;
#pragma unroll
        for (int off = 1; off < 32; off <<= 1) {
            int u = __shfl_up_sync(0xffffffffu, wv, off);
            if (lane >= off) wv += u;
        }
        warp_sums[lane] = wv - w;   // exclusive warp offsets
    }
    __syncthreads();
    int excl = (v - s) + warp_sums[wid];   // exclusive prefix for this thread

    // pass B: write rowptr + norm
    int acc = excl;
#pragma unroll 7
    for (int j = 0; j < SCAN_PER; j++) {
        int i = base + j;
        if (i < N_NODES) {
            int c = g_cnt[i];
            g_rowptr[i] = acc;
            acc += c;
            g_norm[i] = rsqrtf(fmaxf((float)c, 1.0f));
        }
    }
    if (t == SCAN_T - 1) g_rowptr[N_NODES] = N_EDGES;
}

// ---------------------------------------------------------------------------
// CSR fill: atomic-free scatter using precomputed ranks.
// ---------------------------------------------------------------------------
__global__ void k_fill(const int* __restrict__ src,
                       const int* __restrict__ dst) {
    int e = blockIdx.x * blockDim.x + threadIdx.x;
    if (e < N_EDGES) {
        int d = dst[e];
        g_csr_src[g_rowptr[d] + g_rank[e]] = src[e];
    }
}

// ---------------------------------------------------------------------------
// Pull-mode hop: warp per dst node.
//   out[d] = norm[d] * sum_{s in N(d)} norm[s] * in[s]
// Lane carries one float4 (32 lanes * 4 = 128 cols). No atomics.
// ---------------------------------------------------------------------------
template <int HOP>
__global__ void __launch_bounds__(256) k_hop(const float* __restrict__ feat) {
    int w    = (blockIdx.x * blockDim.x + threadIdx.x) >> 5;
    int lane = threadIdx.x & 31;
    if (w >= N_NODES) return;

    const float* in  = (HOP == 1) ? feat   : g_buf0;
    float*       out = (HOP == 1) ? g_buf0 : g_buf1;

    int beg = g_rowptr[w];
    int end = g_rowptr[w + 1];
    float4 acc = make_float4(0.f, 0.f, 0.f, 0.f);
    const float4* in4 = (const float4*)in;
    int e = beg;
    for (; e + 4 <= end; e += 4) {
        int s0 = g_csr_src[e + 0], s1 = g_csr_src[e + 1];
        int s2 = g_csr_src[e + 2], s3 = g_csr_src[e + 3];
        float n0 = g_norm[s0], n1 = g_norm[s1], n2 = g_norm[s2], n3 = g_norm[s3];
        float4 v0 = __ldg(in4 + s0 * 32 + lane);
        float4 v1 = __ldg(in4 + s1 * 32 + lane);
        float4 v2 = __ldg(in4 + s2 * 32 + lane);
        float4 v3 = __ldg(in4 + s3 * 32 + lane);
        acc.x += n0 * v0.x + n1 * v1.x + n2 * v2.x + n3 * v3.x;
        acc.y += n0 * v0.y + n1 * v1.y + n2 * v2.y + n3 * v3.y;
        acc.z += n0 * v0.z + n1 * v1.z + n2 * v2.z + n3 * v3.z;
        acc.w += n0 * v0.w + n1 * v1.w + n2 * v2.w + n3 * v3.w;
    }
    for (; e < end; e++) {
        int s = g_csr_src[e];
        float ns = g_norm[s];
        float4 v = __ldg(in4 + s * 32 + lane);
        acc.x += ns * v.x; acc.y += ns * v.y;
        acc.z += ns * v.z; acc.w += ns * v.w;
    }
    float nd = g_norm[w];
    acc.x *= nd; acc.y *= nd; acc.z *= nd; acc.w *= nd;
    ((float4*)out)[w * 32 + lane] = acc;
}

// ---------------------------------------------------------------------------
// GEMM: out[n][o] = sum_k buf1[n][k] * W[o][k] + b[o]
// 128x128 block tile, BK=32, 256 threads, 8x8 micro-tile, float4 smem reads.
// smem row stride 132 (mult of 4 -> 16B-aligned float4 rows).
// ---------------------------------------------------------------------------
#define GBM 128
#define GBK 32
#define GPAD 132
__global__ void __launch_bounds__(256) k_gemm(const float* __restrict__ W,
                                              const float* __restrict__ bias,
                                              float* __restrict__ out) {
    __shared__ float As[GBK][GPAD];   // [k][row]
    __shared__ float Bs[GBK][GPAD];   // [k][col]

    int t  = threadIdx.x;       // 0..255
    int tx = t & 15;            // col group: cols tx*8..tx*8+7
    int ty = t >> 4;            // row group: rows ty*8..ty*8+7
    int row0 = blockIdx.x * GBM;

    float acc[8][8];
#pragma unroll
    for (int i = 0; i < 8; i++)
#pragma unroll
        for (int j = 0; j < 8; j++) acc[i][j] = 0.f;

    for (int k0 = 0; k0 < D; k0 += GBK) {
        // A tile: 128 rows x 32 k = 1024 float4; 4 per thread.
#pragma unroll
        for (int i = 0; i < 4; i++) {
            int f  = t + i * 256;
            int r  = f >> 3;            // 0..127
            int kc = (f & 7) * 4;       // 0,4,...,28
            int rg = row0 + r;
            float4 v = make_float4(0.f, 0.f, 0.f, 0.f);
            if (rg < N_NODES)
                v = *(const float4*)&g_buf1[(size_t)rg * D + k0 + kc];
            As[kc + 0][r] = v.x; As[kc + 1][r] = v.y;
            As[kc + 2][r] = v.z; As[kc + 3][r] = v.w;
        }
        // B tile: 128 o x 32 k.
#pragma unroll
        for (int i = 0; i < 4; i++) {
            int f  = t + i * 256;
            int o  = f >> 3;
            int kc = (f & 7) * 4;
            float4 v = *(const float4*)&W[o * D + k0 + kc];
            Bs[kc + 0][o] = v.x; Bs[kc + 1][o] = v.y;
            Bs[kc + 2][o] = v.z; Bs[kc + 3][o] = v.w;
        }
        __syncthreads();

#pragma unroll
        for (int kk = 0; kk < GBK; kk++) {
            float4 a0 = *(const float4*)&As[kk][ty * 8];
            float4 a1 = *(const float4*)&As[kk][ty * 8 + 4];
            float4 b0 = *(const float4*)&Bs[kk][tx * 8];
            float4 b1 = *(const float4*)&Bs[kk][tx * 8 + 4];
            float a[8] = {a0.x, a0.y, a0.z, a0.w, a1.x, a1.y, a1.z, a1.w};
            float b[8] = {b0.x, b0.y, b0.z, b0.w, b1.x, b1.y, b1.z, b1.w};
#pragma unroll
            for (int i = 0; i < 8; i++)
#pragma unroll
                for (int j = 0; j < 8; j++) acc[i][j] += a[i] * b[j];
        }
        __syncthreads();
    }

#pragma unroll
    for (int i = 0; i < 8; i++) {
        int rg = row0 + ty * 8 + i;
        if (rg >= N_NODES) continue;
#pragma unroll
        for (int j = 0; j < 8; j += 4) {
            int c = tx * 8 + j;
            float4 r;
            r.x = acc[i][j + 0] + bias[c + 0];
            r.y = acc[i][j + 1] + bias[c + 1];
            r.z = acc[i][j + 2] + bias[c + 2];
            r.w = acc[i][j + 3] + bias[c + 3];
            *(float4*)&out[(size_t)rg * D + c] = r;
        }
    }
}

// ---------------------------------------------------------------------------
// kernel_launch
// ---------------------------------------------------------------------------
extern "C" void kernel_launch(void* const* d_in, const int* in_sizes, int n_in,
                              void* d_out, int out_size) {
    const float* feat = (const float*)d_in[0];
    const int*   src  = (const int*)d_in[1];
    const int*   dst  = (const int*)d_in[2];
    const float* W    = (const float*)d_in[3];
    const float* bias = (const float*)d_in[4];
    float*       out  = (float*)d_out;

    const int gEdge = (N_EDGES + 255) / 256;
    const int gHop  = (N_NODES * 32 + 255) / 256;   // warp per node
    const int gGemm = (N_NODES + GBM - 1) / GBM;    // 391

    void* cnt_ptr = nullptr;
    cudaGetSymbolAddress(&cnt_ptr, g_cnt);
    cudaMemsetAsync(cnt_ptr, 0, N_NODES * sizeof(int), 0);

    k_deg_rank<<<gEdge, 256>>>(dst);
    k_scan    <<<1, SCAN_T>>>();
    k_fill    <<<gEdge, 256>>>(src, dst);
    k_hop<1>  <<<gHop, 256>>>(feat);    // feat   -> g_buf0
    k_hop<2>  <<<gHop, 256>>>(feat);    // g_buf0 -> g_buf1
    k_gemm    <<<gGemm, 256>>>(W, bias, out);
}

// round 6
// speedup vs baseline: 1.2856x; 1.2856x over previous
#include <cuda_runtime.h>

#define N_NODES 50000
#define N_EDGES 1600000
#define D 128

#define SCAN_B 1024
#define SCAN_NBLK ((N_NODES + SCAN_B - 1) / SCAN_B)   // 49

// Scratch (allocation-free rule: __device__ globals)
__device__ float g_buf0[N_NODES * D];
__device__ float g_buf1[N_NODES * D];
__device__ int   g_cnt[N_NODES];          // in-degree histogram
__device__ int   g_cur[N_NODES];          // CSR fill cursors
__device__ int   g_rowptr[N_NODES + 1];
__device__ int   g_csr_src[N_EDGES];
__device__ float g_norm[N_NODES];
__device__ int   g_blocksum[SCAN_NBLK];

// ---------------------------------------------------------------------------
// In-degree histogram (int atomics).
// ---------------------------------------------------------------------------
__global__ void k_deg(const int* __restrict__ dst) {
    int e = blockIdx.x * blockDim.x + threadIdx.x;
    if (e < N_EDGES) atomicAdd(&g_cnt[dst[e]], 1);
}

// ---------------------------------------------------------------------------
// Scan pass 1: per-block exclusive scan of g_cnt into g_rowptr, block totals.
// ---------------------------------------------------------------------------
__global__ void __launch_bounds__(SCAN_B) k_scan1() {
    __shared__ int sh[SCAN_B];
    int i = blockIdx.x * SCAN_B + threadIdx.x;
    int v = (i < N_NODES) ? g_cnt[i] : 0;
    sh[threadIdx.x] = v;
    __syncthreads();
#pragma unroll
    for (int off = 1; off < SCAN_B; off <<= 1) {
        int t = (threadIdx.x >= off) ? sh[threadIdx.x - off] : 0;
        __syncthreads();
        sh[threadIdx.x] += t;
        __syncthreads();
    }
    if (i < N_NODES) g_rowptr[i] = sh[threadIdx.x] - v;  // exclusive, local
    if (threadIdx.x == SCAN_B - 1) g_blocksum[blockIdx.x] = sh[SCAN_B - 1];
}

// ---------------------------------------------------------------------------
// Scan pass 2 (fused offset): each block sums the block-sums below it via
// shared atomics (<=48 adds), then adds offset, computes norm, closes rowptr.
// ---------------------------------------------------------------------------
__global__ void __launch_bounds__(SCAN_B) k_scan2() {
    __shared__ int off;
    int t = threadIdx.x;
    if (t == 0) off = 0;
    __syncthreads();
    if (t < SCAN_NBLK && t < blockIdx.x) atomicAdd(&off, g_blocksum[t]);
    __syncthreads();
    int o = off;
    int i = blockIdx.x * SCAN_B + t;
    if (i < N_NODES) {
        g_rowptr[i] += o;
        g_norm[i] = rsqrtf(fmaxf((float)g_cnt[i], 1.0f));
    }
    if (i == 0) g_rowptr[N_NODES] = N_EDGES;
}

// ---------------------------------------------------------------------------
// CSR fill: scatter src indices into per-dst contiguous lists.
// ---------------------------------------------------------------------------
__global__ void k_fill(const int* __restrict__ src,
                       const int* __restrict__ dst) {
    int e = blockIdx.x * blockDim.x + threadIdx.x;
    if (e < N_EDGES) {
        int d = dst[e];
        int p = atomicAdd(&g_cur[d], 1);
        g_csr_src[g_rowptr[d] + p] = src[e];
    }
}

// ---------------------------------------------------------------------------
// Pull-mode hop: warp per dst node.
//   out[d] = norm[d] * sum_{s in N(d)} norm[s] * in[s]
// Lane carries one float4 (32 lanes * 4 = 128 cols). No atomics.
// ---------------------------------------------------------------------------
template <int HOP>
__global__ void __launch_bounds__(256) k_hop(const float* __restrict__ feat) {
    int w    = (blockIdx.x * blockDim.x + threadIdx.x) >> 5;
    int lane = threadIdx.x & 31;
    if (w >= N_NODES) return;

    const float* in  = (HOP == 1) ? feat   : g_buf0;
    float*       out = (HOP == 1) ? g_buf0 : g_buf1;

    int beg = g_rowptr[w];
    int end = g_rowptr[w + 1];
    float4 acc = make_float4(0.f, 0.f, 0.f, 0.f);
    const float4* in4 = (const float4*)in;
    int e = beg;
    for (; e + 4 <= end; e += 4) {
        int s0 = g_csr_src[e + 0], s1 = g_csr_src[e + 1];
        int s2 = g_csr_src[e + 2], s3 = g_csr_src[e + 3];
        float n0 = g_norm[s0], n1 = g_norm[s1], n2 = g_norm[s2], n3 = g_norm[s3];
        float4 v0 = __ldg(in4 + s0 * 32 + lane);
        float4 v1 = __ldg(in4 + s1 * 32 + lane);
        float4 v2 = __ldg(in4 + s2 * 32 + lane);
        float4 v3 = __ldg(in4 + s3 * 32 + lane);
        acc.x += n0 * v0.x + n1 * v1.x + n2 * v2.x + n3 * v3.x;
        acc.y += n0 * v0.y + n1 * v1.y + n2 * v2.y + n3 * v3.y;
        acc.z += n0 * v0.z + n1 * v1.z + n2 * v2.z + n3 * v3.z;
        acc.w += n0 * v0.w + n1 * v1.w + n2 * v2.w + n3 * v3.w;
    }
    for (; e < end; e++) {
        int s = g_csr_src[e];
        float ns = g_norm[s];
        float4 v = __ldg(in4 + s * 32 + lane);
        acc.x += ns * v.x; acc.y += ns * v.y;
        acc.z += ns * v.z; acc.w += ns * v.w;
    }
    float nd = g_norm[w];
    acc.x *= nd; acc.y *= nd; acc.z *= nd; acc.w *= nd;
    ((float4*)out)[w * 32 + lane] = acc;
}

// ---------------------------------------------------------------------------
// GEMM: out[n][o] = sum_k buf1[n][k] * W[o][k] + b[o]  (buf1 pre-normalized)
// Known-good 64x128 tile from the 200.7us run.
// ---------------------------------------------------------------------------
#define BM 64
#define BK 32
__global__ void __launch_bounds__(256) k_gemm(const float* __restrict__ W,
                                              const float* __restrict__ bias,
                                              float* __restrict__ out) {
    __shared__ float As[BK][BM + 1];
    __shared__ float Bs[BK][D + 1];

    int t  = threadIdx.x;
    int tx = t & 15;
    int ty = t >> 4;
    int row0 = blockIdx.x * BM;

    float acc[4][8];
#pragma unroll
    for (int i = 0; i < 4; i++)
#pragma unroll
        for (int j = 0; j < 8; j++) acc[i][j] = 0.f;

    for (int k0 = 0; k0 < D; k0 += BK) {
#pragma unroll
        for (int i = 0; i < 8; i++) {
            int idx = t + i * 256;
            int r  = idx >> 5;
            int kk = idx & 31;
            int rg = row0 + r;
            float v = 0.f;
            if (rg < N_NODES) v = g_buf1[(size_t)rg * D + k0 + kk];
            As[kk][r] = v;
        }
#pragma unroll
        for (int i = 0; i < 16; i++) {
            int idx = t + i * 256;
            int o  = idx >> 5;
            int kk = idx & 31;
            Bs[kk][o] = W[o * D + k0 + kk];
        }
        __syncthreads();

#pragma unroll
        for (int kk = 0; kk < BK; kk++) {
            float a[4], bv[8];
#pragma unroll
            for (int i = 0; i < 4; i++) a[i] = As[kk][ty * 4 + i];
#pragma unroll
            for (int j = 0; j < 8; j++) bv[j] = Bs[kk][tx + 16 * j];
#pragma unroll
            for (int i = 0; i < 4; i++)
#pragma unroll
                for (int j = 0; j < 8; j++) acc[i][j] += a[i] * bv[j];
        }
        __syncthreads();
    }

#pragma unroll
    for (int i = 0; i < 4; i++) {
        int rg = row0 + ty * 4 + i;
        if (rg >= N_NODES) continue;
#pragma unroll
        for (int j = 0; j < 8; j++) {
            int c = tx + 16 * j;
            out[(size_t)rg * D + c] = acc[i][j] + bias[c];
        }
    }
}

// ---------------------------------------------------------------------------
// kernel_launch
// ---------------------------------------------------------------------------
extern "C" void kernel_launch(void* const* d_in, const int* in_sizes, int n_in,
                              void* d_out, int out_size) {
    const float* feat = (const float*)d_in[0];
    const int*   src  = (const int*)d_in[1];
    const int*   dst  = (const int*)d_in[2];
    const float* W    = (const float*)d_in[3];
    const float* bias = (const float*)d_in[4];
    float*       out  = (float*)d_out;

    const int gEdge = (N_EDGES + 255) / 256;
    const int gHop  = (N_NODES * 32 + 255) / 256;   // warp per node
    const int gGemm = (N_NODES + BM - 1) / BM;

    void* p = nullptr;
    cudaGetSymbolAddress(&p, g_cnt);
    cudaMemsetAsync(p, 0, N_NODES * sizeof(int), 0);
    cudaGetSymbolAddress(&p, g_cur);
    cudaMemsetAsync(p, 0, N_NODES * sizeof(int), 0);

    k_deg  <<<gEdge, 256>>>(dst);
    k_scan1<<<SCAN_NBLK, SCAN_B>>>();
    k_scan2<<<SCAN_NBLK, SCAN_B>>>();
    k_fill <<<gEdge, 256>>>(src, dst);
    k_hop<1><<<gHop, 256>>>(feat);    // feat   -> g_buf0
    k_hop<2><<<gHop, 256>>>(feat);    // g_buf0 -> g_buf1
    k_gemm <<<gGemm, 256>>>(W, bias, out);
}

// round 7
// speedup vs baseline: 1.3013x; 1.0122x over previous
#include <cuda_runtime.h>

#define N_NODES 50000
#define N_EDGES 1600000
#define D 128

#define SCAN_B 1024
#define SCAN_NBLK ((N_NODES + SCAN_B - 1) / SCAN_B)   // 49

// Scratch (allocation-free rule: __device__ globals)
__device__ float g_buf0[N_NODES * D];
__device__ float g_buf1[N_NODES * D];
__device__ int   g_cnt[N_NODES];          // in-degree histogram
__device__ int   g_rank[N_EDGES];         // edge rank within its dst list
__device__ int   g_rowptr[N_NODES + 1];
__device__ int   g_csr_src[N_EDGES];
__device__ float g_norm[N_NODES];
__device__ int   g_blocksum[SCAN_NBLK];

// ---------------------------------------------------------------------------
// Degree histogram; atomic return value = this edge's rank within its dst.
// ---------------------------------------------------------------------------
__global__ void k_deg_rank(const int* __restrict__ dst) {
    int e = blockIdx.x * blockDim.x + threadIdx.x;
    if (e < N_EDGES) {
        g_rank[e] = atomicAdd(&g_cnt[dst[e]], 1);
    }
}

// ---------------------------------------------------------------------------
// Scan pass 1: per-block exclusive scan of g_cnt into g_rowptr, block totals.
// ---------------------------------------------------------------------------
__global__ void __launch_bounds__(SCAN_B) k_scan1() {
    __shared__ int sh[SCAN_B];
    int i = blockIdx.x * SCAN_B + threadIdx.x;
    int v = (i < N_NODES) ? g_cnt[i] : 0;
    sh[threadIdx.x] = v;
    __syncthreads();
#pragma unroll
    for (int off = 1; off < SCAN_B; off <<= 1) {
        int t = (threadIdx.x >= off) ? sh[threadIdx.x - off] : 0;
        __syncthreads();
        sh[threadIdx.x] += t;
        __syncthreads();
    }
    if (i < N_NODES) g_rowptr[i] = sh[threadIdx.x] - v;  // exclusive, local
    if (threadIdx.x == SCAN_B - 1) g_blocksum[blockIdx.x] = sh[SCAN_B - 1];
}

// ---------------------------------------------------------------------------
// Scan pass 2: block offsets via shared atomics, + norm, close rowptr.
// ---------------------------------------------------------------------------
__global__ void __launch_bounds__(SCAN_B) k_scan2() {
    __shared__ int off;
    int t = threadIdx.x;
    if (t == 0) off = 0;
    __syncthreads();
    if (t < SCAN_NBLK && t < blockIdx.x) atomicAdd(&off, g_blocksum[t]);
    __syncthreads();
    int o = off;
    int i = blockIdx.x * SCAN_B + t;
    if (i < N_NODES) {
        g_rowptr[i] += o;
        g_norm[i] = rsqrtf(fmaxf((float)g_cnt[i], 1.0f));
    }
    if (i == 0) g_rowptr[N_NODES] = N_EDGES;
}

// ---------------------------------------------------------------------------
// CSR fill: atomic-free scatter using precomputed ranks.
// ---------------------------------------------------------------------------
__global__ void k_fill(const int* __restrict__ src,
                       const int* __restrict__ dst) {
    int e = blockIdx.x * blockDim.x + threadIdx.x;
    if (e < N_EDGES) {
        int d = dst[e];
        g_csr_src[g_rowptr[d] + g_rank[e]] = src[e];
    }
}

// ---------------------------------------------------------------------------
// Pull-mode hop: warp per dst node.
//   out[d] = norm[d] * sum_{s in N(d)} norm[s] * in[s]
// Lane carries one float4. Unroll 8 for deeper MLP on the gathers.
// ---------------------------------------------------------------------------
template <int HOP>
__global__ void __launch_bounds__(256) k_hop(const float* __restrict__ feat) {
    int w    = (blockIdx.x * blockDim.x + threadIdx.x) >> 5;
    int lane = threadIdx.x & 31;
    if (w >= N_NODES) return;

    const float* in  = (HOP == 1) ? feat   : g_buf0;
    float*       out = (HOP == 1) ? g_buf0 : g_buf1;

    int beg = g_rowptr[w];
    int end = g_rowptr[w + 1];
    float4 acc = make_float4(0.f, 0.f, 0.f, 0.f);
    float4 acc2 = make_float4(0.f, 0.f, 0.f, 0.f);
    const float4* in4 = (const float4*)in;
    int e = beg;
    for (; e + 8 <= end; e += 8) {
        int s0 = __ldg(&g_csr_src[e + 0]), s1 = __ldg(&g_csr_src[e + 1]);
        int s2 = __ldg(&g_csr_src[e + 2]), s3 = __ldg(&g_csr_src[e + 3]);
        int s4 = __ldg(&g_csr_src[e + 4]), s5 = __ldg(&g_csr_src[e + 5]);
        int s6 = __ldg(&g_csr_src[e + 6]), s7 = __ldg(&g_csr_src[e + 7]);
        float n0 = __ldg(&g_norm[s0]), n1 = __ldg(&g_norm[s1]);
        float n2 = __ldg(&g_norm[s2]), n3 = __ldg(&g_norm[s3]);
        float n4 = __ldg(&g_norm[s4]), n5 = __ldg(&g_norm[s5]);
        float n6 = __ldg(&g_norm[s6]), n7 = __ldg(&g_norm[s7]);
        float4 v0 = __ldg(in4 + s0 * 32 + lane);
        float4 v1 = __ldg(in4 + s1 * 32 + lane);
        float4 v2 = __ldg(in4 + s2 * 32 + lane);
        float4 v3 = __ldg(in4 + s3 * 32 + lane);
        float4 v4 = __ldg(in4 + s4 * 32 + lane);
        float4 v5 = __ldg(in4 + s5 * 32 + lane);
        float4 v6 = __ldg(in4 + s6 * 32 + lane);
        float4 v7 = __ldg(in4 + s7 * 32 + lane);
        acc.x  += n0 * v0.x + n1 * v1.x + n2 * v2.x + n3 * v3.x;
        acc.y  += n0 * v0.y + n1 * v1.y + n2 * v2.y + n3 * v3.y;
        acc.z  += n0 * v0.z + n1 * v1.z + n2 * v2.z + n3 * v3.z;
        acc.w  += n0 * v0.w + n1 * v1.w + n2 * v2.w + n3 * v3.w;
        acc2.x += n4 * v4.x + n5 * v5.x + n6 * v6.x + n7 * v7.x;
        acc2.y += n4 * v4.y + n5 * v5.y + n6 * v6.y + n7 * v7.y;
        acc2.z += n4 * v4.z + n5 * v5.z + n6 * v6.z + n7 * v7.z;
        acc2.w += n4 * v4.w + n5 * v5.w + n6 * v6.w + n7 * v7.w;
    }
    for (; e + 4 <= end; e += 4) {
        int s0 = __ldg(&g_csr_src[e + 0]), s1 = __ldg(&g_csr_src[e + 1]);
        int s2 = __ldg(&g_csr_src[e + 2]), s3 = __ldg(&g_csr_src[e + 3]);
        float n0 = __ldg(&g_norm[s0]), n1 = __ldg(&g_norm[s1]);
        float n2 = __ldg(&g_norm[s2]), n3 = __ldg(&g_norm[s3]);
        float4 v0 = __ldg(in4 + s0 * 32 + lane);
        float4 v1 = __ldg(in4 + s1 * 32 + lane);
        float4 v2 = __ldg(in4 + s2 * 32 + lane);
        float4 v3 = __ldg(in4 + s3 * 32 + lane);
        acc.x += n0 * v0.x + n1 * v1.x + n2 * v2.x + n3 * v3.x;
        acc.y += n0 * v0.y + n1 * v1.y + n2 * v2.y + n3 * v3.y;
        acc.z += n0 * v0.z + n1 * v1.z + n2 * v2.z + n3 * v3.z;
        acc.w += n0 * v0.w + n1 * v1.w + n2 * v2.w + n3 * v3.w;
    }
    for (; e < end; e++) {
        int s = __ldg(&g_csr_src[e]);
        float ns = __ldg(&g_norm[s]);
        float4 v = __ldg(in4 + s * 32 + lane);
        acc.x += ns * v.x; acc.y += ns * v.y;
        acc.z += ns * v.z; acc.w += ns * v.w;
    }
    acc.x += acc2.x; acc.y += acc2.y; acc.z += acc2.z; acc.w += acc2.w;
    float nd = g_norm[w];
    acc.x *= nd; acc.y *= nd; acc.z *= nd; acc.w *= nd;
    ((float4*)out)[w * 32 + lane] = acc;
}

// ---------------------------------------------------------------------------
// GEMM: out[n][o] = sum_k buf1[n][k] * W[o][k] + b[o]  (buf1 pre-normalized)
// Known-good 64x128 tile.
// ---------------------------------------------------------------------------
#define BM 64
#define BK 32
__global__ void __launch_bounds__(256) k_gemm(const float* __restrict__ W,
                                              const float* __restrict__ bias,
                                              float* __restrict__ out) {
    __shared__ float As[BK][BM + 1];
    __shared__ float Bs[BK][D + 1];

    int t  = threadIdx.x;
    int tx = t & 15;
    int ty = t >> 4;
    int row0 = blockIdx.x * BM;

    float acc[4][8];
#pragma unroll
    for (int i = 0; i < 4; i++)
#pragma unroll
        for (int j = 0; j < 8; j++) acc[i][j] = 0.f;

    for (int k0 = 0; k0 < D; k0 += BK) {
#pragma unroll
        for (int i = 0; i < 8; i++) {
            int idx = t + i * 256;
            int r  = idx >> 5;
            int kk = idx & 31;
            int rg = row0 + r;
            float v = 0.f;
            if (rg < N_NODES) v = g_buf1[(size_t)rg * D + k0 + kk];
            As[kk][r] = v;
        }
#pragma unroll
        for (int i = 0; i < 16; i++) {
            int idx = t + i * 256;
            int o  = idx >> 5;
            int kk = idx & 31;
            Bs[kk][o] = W[o * D + k0 + kk];
        }
        __syncthreads();

#pragma unroll
        for (int kk = 0; kk < BK; kk++) {
            float a[4], bv[8];
#pragma unroll
            for (int i = 0; i < 4; i++) a[i] = As[kk][ty * 4 + i];
#pragma unroll
            for (int j = 0; j < 8; j++) bv[j] = Bs[kk][tx + 16 * j];
#pragma unroll
            for (int i = 0; i < 4; i++)
#pragma unroll
                for (int j = 0; j < 8; j++) acc[i][j] += a[i] * bv[j];
        }
        __syncthreads();
    }

#pragma unroll
    for (int i = 0; i < 4; i++) {
        int rg = row0 + ty * 4 + i;
        if (rg >= N_NODES) continue;
#pragma unroll
        for (int j = 0; j < 8; j++) {
            int c = tx + 16 * j;
            out[(size_t)rg * D + c] = acc[i][j] + bias[c];
        }
    }
}

// ---------------------------------------------------------------------------
// kernel_launch
// ---------------------------------------------------------------------------
extern "C" void kernel_launch(void* const* d_in, const int* in_sizes, int n_in,
                              void* d_out, int out_size) {
    const float* feat = (const float*)d_in[0];
    const int*   src  = (const int*)d_in[1];
    const int*   dst  = (const int*)d_in[2];
    const float* W    = (const float*)d_in[3];
    const float* bias = (const float*)d_in[4];
    float*       out  = (float*)d_out;

    const int gEdge = (N_EDGES + 255) / 256;
    const int gHop  = (N_NODES * 32 + 255) / 256;   // warp per node
    const int gGemm = (N_NODES + BM - 1) / BM;

    void* p = nullptr;
    cudaGetSymbolAddress(&p, g_cnt);
    cudaMemsetAsync(p, 0, N_NODES * sizeof(int), 0);

    k_deg_rank<<<gEdge, 256>>>(dst);
    k_scan1   <<<SCAN_NBLK, SCAN_B>>>();
    k_scan2   <<<SCAN_NBLK, SCAN_B>>>();
    k_fill    <<<gEdge, 256>>>(src, dst);
    k_hop<1>  <<<gHop, 256>>>(feat);    // feat   -> g_buf0
    k_hop<2>  <<<gHop, 256>>>(feat);    // g_buf0 -> g_buf1
    k_gemm    <<<gGemm, 256>>>(W, bias, out);
}

// round 8
// speedup vs baseline: 1.3159x; 1.0112x over previous
#include <cuda_runtime.h>
#include <cuda_fp16.h>

#define N_NODES 50000
#define N_EDGES 1600000
#define D 128

#define SCAN_B 1024
#define SCAN_NBLK ((N_NODES + SCAN_B - 1) / SCAN_B)   // 49

// Scratch (allocation-free rule: __device__ globals)
__device__ __half g_buf0h[N_NODES * D];   // hop-1 output, fp16
__device__ float  g_buf1[N_NODES * D];    // hop-2 output, fp32 (GEMM input)
__device__ int    g_cnt[N_NODES];
__device__ int    g_rank[N_EDGES];
__device__ int    g_rowptr[N_NODES + 1];
__device__ int    g_csr_src[N_EDGES];
__device__ float  g_norm[N_NODES];
__device__ int    g_blocksum[SCAN_NBLK];

// ---------------------------------------------------------------------------
// Degree histogram; atomic return value = this edge's rank within its dst.
// ---------------------------------------------------------------------------
__global__ void k_deg_rank(const int* __restrict__ dst) {
    int e = blockIdx.x * blockDim.x + threadIdx.x;
    if (e < N_EDGES) {
        g_rank[e] = atomicAdd(&g_cnt[dst[e]], 1);
    }
}

// ---------------------------------------------------------------------------
// Scan pass 1: per-block exclusive scan of g_cnt into g_rowptr, block totals.
// ---------------------------------------------------------------------------
__global__ void __launch_bounds__(SCAN_B) k_scan1() {
    __shared__ int sh[SCAN_B];
    int i = blockIdx.x * SCAN_B + threadIdx.x;
    int v = (i < N_NODES) ? g_cnt[i] : 0;
    sh[threadIdx.x] = v;
    __syncthreads();
#pragma unroll
    for (int off = 1; off < SCAN_B; off <<= 1) {
        int t = (threadIdx.x >= off) ? sh[threadIdx.x - off] : 0;
        __syncthreads();
        sh[threadIdx.x] += t;
        __syncthreads();
    }
    if (i < N_NODES) g_rowptr[i] = sh[threadIdx.x] - v;  // exclusive, local
    if (threadIdx.x == SCAN_B - 1) g_blocksum[blockIdx.x] = sh[SCAN_B - 1];
}

// ---------------------------------------------------------------------------
// Scan pass 2: block offsets via shared atomics, + norm, close rowptr.
// ---------------------------------------------------------------------------
__global__ void __launch_bounds__(SCAN_B) k_scan2() {
    __shared__ int off;
    int t = threadIdx.x;
    if (t == 0) off = 0;
    __syncthreads();
    if (t < SCAN_NBLK && t < blockIdx.x) atomicAdd(&off, g_blocksum[t]);
    __syncthreads();
    int o = off;
    int i = blockIdx.x * SCAN_B + t;
    if (i < N_NODES) {
        g_rowptr[i] += o;
        g_norm[i] = rsqrtf(fmaxf((float)g_cnt[i], 1.0f));
    }
    if (i == 0) g_rowptr[N_NODES] = N_EDGES;
}

// ---------------------------------------------------------------------------
// CSR fill: atomic-free scatter, 4 edges per thread for MLP.
// ---------------------------------------------------------------------------
__global__ void k_fill(const int* __restrict__ src,
                       const int* __restrict__ dst) {
    int base = (blockIdx.x * blockDim.x + threadIdx.x) * 4;
#pragma unroll
    for (int j = 0; j < 4; j++) {
        int e = base + j;
        if (e < N_EDGES) {
            int d = dst[e];
            g_csr_src[g_rowptr[d] + g_rank[e]] = src[e];
        }
    }
}

// ---------------------------------------------------------------------------
// Hop 1: gather fp32 feat rows, write fp16.
//   out[d] = norm[d] * sum_{s in N(d)} norm[s] * feat[s]
// Warp per dst node; lane carries 4 columns.
// ---------------------------------------------------------------------------
__global__ void __launch_bounds__(256) k_hop1(const float* __restrict__ feat) {
    int w    = (blockIdx.x * blockDim.x + threadIdx.x) >> 5;
    int lane = threadIdx.x & 31;
    if (w >= N_NODES) return;

    int beg = g_rowptr[w];
    int end = g_rowptr[w + 1];
    float4 acc = make_float4(0.f, 0.f, 0.f, 0.f);
    const float4* in4 = (const float4*)feat;
    int e = beg;
    for (; e + 4 <= end; e += 4) {
        int s0 = __ldg(&g_csr_src[e + 0]), s1 = __ldg(&g_csr_src[e + 1]);
        int s2 = __ldg(&g_csr_src[e + 2]), s3 = __ldg(&g_csr_src[e + 3]);
        float n0 = __ldg(&g_norm[s0]), n1 = __ldg(&g_norm[s1]);
        float n2 = __ldg(&g_norm[s2]), n3 = __ldg(&g_norm[s3]);
        float4 v0 = __ldg(in4 + s0 * 32 + lane);
        float4 v1 = __ldg(in4 + s1 * 32 + lane);
        float4 v2 = __ldg(in4 + s2 * 32 + lane);
        float4 v3 = __ldg(in4 + s3 * 32 + lane);
        acc.x += n0 * v0.x + n1 * v1.x + n2 * v2.x + n3 * v3.x;
        acc.y += n0 * v0.y + n1 * v1.y + n2 * v2.y + n3 * v3.y;
        acc.z += n0 * v0.z + n1 * v1.z + n2 * v2.z + n3 * v3.z;
        acc.w += n0 * v0.w + n1 * v1.w + n2 * v2.w + n3 * v3.w;
    }
    for (; e < end; e++) {
        int s = __ldg(&g_csr_src[e]);
        float ns = __ldg(&g_norm[s]);
        float4 v = __ldg(in4 + s * 32 + lane);
        acc.x += ns * v.x; acc.y += ns * v.y;
        acc.z += ns * v.z; acc.w += ns * v.w;
    }
    float nd = g_norm[w];
    acc.x *= nd; acc.y *= nd; acc.z *= nd; acc.w *= nd;

    __half2 h0 = __floats2half2_rn(acc.x, acc.y);
    __half2 h1 = __floats2half2_rn(acc.z, acc.w);
    uint2 u;
    u.x = *(unsigned int*)&h0;
    u.y = *(unsigned int*)&h1;
    ((uint2*)g_buf0h)[w * 32 + lane] = u;   // 8 bytes per lane
}

// ---------------------------------------------------------------------------
// Hop 2: gather fp16 rows (256 B/row), accumulate fp32, write fp32.
// ---------------------------------------------------------------------------
__global__ void __launch_bounds__(256) k_hop2() {
    int w    = (blockIdx.x * blockDim.x + threadIdx.x) >> 5;
    int lane = threadIdx.x & 31;
    if (w >= N_NODES) return;

    int beg = g_rowptr[w];
    int end = g_rowptr[w + 1];
    float4 acc = make_float4(0.f, 0.f, 0.f, 0.f);
    const uint2* in2 = (const uint2*)g_buf0h;   // 32 uint2 per row
    int e = beg;
    for (; e + 4 <= end; e += 4) {
        int s0 = __ldg(&g_csr_src[e + 0]), s1 = __ldg(&g_csr_src[e + 1]);
        int s2 = __ldg(&g_csr_src[e + 2]), s3 = __ldg(&g_csr_src[e + 3]);
        float n0 = __ldg(&g_norm[s0]), n1 = __ldg(&g_norm[s1]);
        float n2 = __ldg(&g_norm[s2]), n3 = __ldg(&g_norm[s3]);
        uint2 u0 = __ldg(in2 + s0 * 32 + lane);
        uint2 u1 = __ldg(in2 + s1 * 32 + lane);
        uint2 u2 = __ldg(in2 + s2 * 32 + lane);
        uint2 u3 = __ldg(in2 + s3 * 32 + lane);
        float2 a0 = __half22float2(*(__half2*)&u0.x), b0 = __half22float2(*(__half2*)&u0.y);
        float2 a1 = __half22float2(*(__half2*)&u1.x), b1 = __half22float2(*(__half2*)&u1.y);
        float2 a2 = __half22float2(*(__half2*)&u2.x), b2 = __half22float2(*(__half2*)&u2.y);
        float2 a3 = __half22float2(*(__half2*)&u3.x), b3 = __half22float2(*(__half2*)&u3.y);
        acc.x += n0 * a0.x + n1 * a1.x + n2 * a2.x + n3 * a3.x;
        acc.y += n0 * a0.y + n1 * a1.y + n2 * a2.y + n3 * a3.y;
        acc.z += n0 * b0.x + n1 * b1.x + n2 * b2.x + n3 * b3.x;
        acc.w += n0 * b0.y + n1 * b1.y + n2 * b2.y + n3 * b3.y;
    }
    for (; e < end; e++) {
        int s = __ldg(&g_csr_src[e]);
        float ns = __ldg(&g_norm[s]);
        uint2 u = __ldg(in2 + s * 32 + lane);
        float2 a = __half22float2(*(__half2*)&u.x);
        float2 b = __half22float2(*(__half2*)&u.y);
        acc.x += ns * a.x; acc.y += ns * a.y;
        acc.z += ns * b.x; acc.w += ns * b.y;
    }
    float nd = g_norm[w];
    acc.x *= nd; acc.y *= nd; acc.z *= nd; acc.w *= nd;
    ((float4*)g_buf1)[w * 32 + lane] = acc;
}

// ---------------------------------------------------------------------------
// GEMM: out[n][o] = sum_k buf1[n][k] * W[o][k] + b[o]  (known-good 64x128 tile)
// ---------------------------------------------------------------------------
#define BM 64
#define BK 32
__global__ void __launch_bounds__(256) k_gemm(const float* __restrict__ W,
                                              const float* __restrict__ bias,
                                              float* __restrict__ out) {
    __shared__ float As[BK][BM + 1];
    __shared__ float Bs[BK][D + 1];

    int t  = threadIdx.x;
    int tx = t & 15;
    int ty = t >> 4;
    int row0 = blockIdx.x * BM;

    float acc[4][8];
#pragma unroll
    for (int i = 0; i < 4; i++)
#pragma unroll
        for (int j = 0; j < 8; j++) acc[i][j] = 0.f;

    for (int k0 = 0; k0 < D; k0 += BK) {
#pragma unroll
        for (int i = 0; i < 8; i++) {
            int idx = t + i * 256;
            int r  = idx >> 5;
            int kk = idx & 31;
            int rg = row0 + r;
            float v = 0.f;
            if (rg < N_NODES) v = g_buf1[(size_t)rg * D + k0 + kk];
            As[kk][r] = v;
        }
#pragma unroll
        for (int i = 0; i < 16; i++) {
            int idx = t + i * 256;
            int o  = idx >> 5;
            int kk = idx & 31;
            Bs[kk][o] = W[o * D + k0 + kk];
        }
        __syncthreads();

#pragma unroll
        for (int kk = 0; kk < BK; kk++) {
            float a[4], bv[8];
#pragma unroll
            for (int i = 0; i < 4; i++) a[i] = As[kk][ty * 4 + i];
#pragma unroll
            for (int j = 0; j < 8; j++) bv[j] = Bs[kk][tx + 16 * j];
#pragma unroll
            for (int i = 0; i < 4; i++)
#pragma unroll
                for (int j = 0; j < 8; j++) acc[i][j] += a[i] * bv[j];
        }
        __syncthreads();
    }

#pragma unroll
    for (int i = 0; i < 4; i++) {
        int rg = row0 + ty * 4 + i;
        if (rg >= N_NODES) continue;
#pragma unroll
        for (int j = 0; j < 8; j++) {
            int c = tx + 16 * j;
            out[(size_t)rg * D + c] = acc[i][j] + bias[c];
        }
    }
}

// ---------------------------------------------------------------------------
// kernel_launch
// ---------------------------------------------------------------------------
extern "C" void kernel_launch(void* const* d_in, const int* in_sizes, int n_in,
                              void* d_out, int out_size) {
    const float* feat = (const float*)d_in[0];
    const int*   src  = (const int*)d_in[1];
    const int*   dst  = (const int*)d_in[2];
    const float* W    = (const float*)d_in[3];
    const float* bias = (const float*)d_in[4];
    float*       out  = (float*)d_out;

    const int gEdge  = (N_EDGES + 255) / 256;
    const int gFill  = (N_EDGES / 4 + 255) / 256;
    const int gHop   = (N_NODES * 32 + 255) / 256;   // warp per node
    const int gGemm  = (N_NODES + BM - 1) / BM;

    void* p = nullptr;
    cudaGetSymbolAddress(&p, g_cnt);
    cudaMemsetAsync(p, 0, N_NODES * sizeof(int), 0);

    k_deg_rank<<<gEdge, 256>>>(dst);
    k_scan1   <<<SCAN_NBLK, SCAN_B>>>();
    k_scan2   <<<SCAN_NBLK, SCAN_B>>>();
    k_fill    <<<gFill, 256>>>(src, dst);
    k_hop1    <<<gHop, 256>>>(feat);    // feat (fp32) -> g_buf0h (fp16)
    k_hop2    <<<gHop, 256>>>();        // g_buf0h     -> g_buf1 (fp32)
    k_gemm    <<<gGemm, 256>>>(W, bias, out);
}